// round 2
// baseline (speedup 1.0000x reference)
#include <cuda_runtime.h>

#define KK     3
#define CIN    16
#define COUT   16
#define HH     64
#define WW     64
#define BB     4

#define TILE_H 2          // output rows per block
#define BX     64
#define BY     2          // 128 threads
#define FG     4          // output channels per block (2 packed f32x2 pairs)

typedef unsigned long long ull;

// ---------------- Blackwell packed f32x2 helpers ----------------
__device__ __forceinline__ ull pk2(float lo, float hi) {
    ull r; asm("mov.b64 %0, {%1, %2};" : "=l"(r) : "f"(lo), "f"(hi)); return r;
}
__device__ __forceinline__ void upk2(ull v, float& lo, float& hi) {
    asm("mov.b64 {%0, %1}, %2;" : "=f"(lo), "=f"(hi) : "l"(v));
}
__device__ __forceinline__ ull ffma2(ull a, ull b, ull c) {
    ull d; asm("fma.rn.f32x2 %0, %1, %2, %3;" : "=l"(d) : "l"(a), "l"(b), "l"(c)); return d;
}
__device__ __forceinline__ ull fmul2(ull a, ull b) {
    ull d; asm("mul.rn.f32x2 %0, %1, %2;" : "=l"(d) : "l"(a), "l"(b)); return d;
}
__device__ __forceinline__ ull fadd2(ull a, ull b) {
    ull d; asm("add.rn.f32x2 %0, %1, %2;" : "=l"(d) : "l"(a), "l"(b)); return d;
}
__device__ __forceinline__ float frcp(float x) {
    float r; asm("rcp.approx.ftz.f32 %0, %1;" : "=f"(r) : "f"(x)); return r;
}

// SMEM:
//  sC: packed coefficients for this block's 4 output channels.
//      Layout per (c, p, q): 10 float2 entries (one ull each):
//        k=0..5 : (A[f0+2q][c][p][k],  A[f0+2q+1][c][p][k])
//        k=6..9 : (Bc[f0+2q][c][p][k-6], Bc[f0+2q+1][c][p][k-6])
//      => 16*9*2*10 = 2880 float2 = 2880 ull = 23040 B, 16B aligned for LDS.128
//  sX: all 16 input-channel tiles, (TILE_H+2) x 66 each = 16*4*66 floats = 16896 B
__global__ __launch_bounds__(BX * BY)
void kaconv_kernel(const float* __restrict__ x,
                   const float* __restrict__ A,
                   const float* __restrict__ Bc,
                   float* __restrict__ out) {
    __shared__ __align__(16) ull  sC[CIN * 9 * 2 * 10];  // 2880 ull = 23040 B
    __shared__ float              sX[CIN * (TILE_H + 2) * 66];

    const int tx  = threadIdx.x;
    const int ty  = threadIdx.y;
    const int tid = ty * BX + tx;
    const int h0  = blockIdx.x * TILE_H;
    const int b   = blockIdx.y;
    const int f0  = blockIdx.z * FG;

    // ---- stage packed coefficients (warp-uniform consumers later) ----
    float2* sCf = reinterpret_cast<float2*>(sC);
    for (int i = tid; i < CIN * 9 * 2 * 10; i += BX * BY) {
        int ii = i;
        const int k = ii % 10; ii /= 10;
        const int q = ii % 2;  ii /= 2;
        const int p = ii % 9;
        const int c = ii / 9;
        const int f = f0 + 2 * q;
        float lo, hi;
        if (k < 6) {
            lo = A[(( f      * CIN + c) * 9 + p) * 6 + k];
            hi = A[(((f + 1) * CIN + c) * 9 + p) * 6 + k];
        } else {
            const int j = k - 6;
            lo = Bc[(( f      * CIN + c) * 9 + p) * 4 + j];
            hi = Bc[(((f + 1) * CIN + c) * 9 + p) * 4 + j];
        }
        sCf[i] = make_float2(lo, hi);
    }

    // ---- stage all 16 input-channel tiles with zero-padded halo ----
    for (int i = tid; i < CIN * (TILE_H + 2) * 66; i += BX * BY) {
        const int col = i % 66;
        const int r   = (i / 66) % (TILE_H + 2);
        const int c   = i / (66 * (TILE_H + 2));
        const int gh  = h0 + r - 1;
        const int gw  = col - 1;
        float v = 0.0f;
        if (gh >= 0 && gh < HH && gw >= 0 && gw < WW)
            v = x[((b * CIN + c) * HH + gh) * WW + gw];
        sX[(c * (TILE_H + 2) + r) * 66 + col] = v;
    }
    __syncthreads();

    const ulonglong2* sC2 = reinterpret_cast<const ulonglong2*>(sC);
    const ull ABSM = 0x7FFFFFFF7FFFFFFFull;
    const ull ONE2 = 0x3F8000003F800000ull;   // (1.0f, 1.0f)

    ull acc0 = 0ull, acc1 = 0ull;             // (+0,+0) packed

    #pragma unroll 1
    for (int c = 0; c < CIN; c++) {
        // register-cache this thread's 3x3 window for channel c
        float xw[9];
        #pragma unroll
        for (int di = 0; di < 3; di++)
            #pragma unroll
            for (int dj = 0; dj < 3; dj++)
                xw[di * 3 + dj] = sX[(c * (TILE_H + 2) + ty + di) * 66 + (tx + dj)];

        // per (c,p): 2 q-groups x 5 ulonglong2 = 10 ulonglong2; per c: 90
        const ulonglong2* pc = sC2 + c * 90;
        #pragma unroll
        for (int p = 0; p < 9; p++) {
            const float xv = xw[p];
            const ull X = pk2(xv, xv);
            const ulonglong2* pp = pc + p * 10;
            #pragma unroll
            for (int q = 0; q < 2; q++) {
                const ulonglong2 u0 = pp[q * 5 + 0];  // {A0, A1}
                const ulonglong2 u1 = pp[q * 5 + 1];  // {A2, A3}
                const ulonglong2 u2 = pp[q * 5 + 2];  // {A4, A5}
                const ulonglong2 u3 = pp[q * 5 + 3];  // {B1, B2}
                const ulonglong2 u4 = pp[q * 5 + 4];  // {B3, B4}

                // P = a0 + a1 x + ... + a5 x^5  (Horner, packed over f-pair)
                ull P = ffma2(u2.y, X, u2.x);
                P = ffma2(P, X, u1.y);
                P = ffma2(P, X, u1.x);
                P = ffma2(P, X, u0.y);
                P = ffma2(P, X, u0.x);

                // S = b1 x + b2 x^2 + b3 x^3 + b4 x^4 = x*(b1 + x*(b2 + x*(b3 + x*b4)))
                ull T = ffma2(u4.y, X, u4.x);
                T = ffma2(T, X, u3.y);
                T = ffma2(T, X, u3.x);
                T = fmul2(T, X);

                // Q = 1 + |S|  (packed abs via AND, packed add)
                const ull Qp = fadd2(ONE2, T & ABSM);
                float q0f, q1f; upk2(Qp, q0f, q1f);
                const ull R = pk2(frcp(q0f), frcp(q1f));

                if (q == 0) acc0 = ffma2(P, R, acc0);
                else        acc1 = ffma2(P, R, acc1);
            }
        }
    }

    // ---- write 4 output channels ----
    const int h = h0 + ty;
    const int w = tx;
    float o0, o1, o2, o3;
    upk2(acc0, o0, o1);
    upk2(acc1, o2, o3);
    float* op = out + ((b * COUT + f0) * HH + h) * WW + w;
    op[0]             = o0;
    op[HH * WW]       = o1;
    op[2 * HH * WW]   = o2;
    op[3 * HH * WW]   = o3;
}

extern "C" void kernel_launch(void* const* d_in, const int* in_sizes, int n_in,
                              void* d_out, int out_size) {
    const float* x  = (const float*)d_in[0];
    const float* A  = (const float*)d_in[1];
    const float* Bc = (const float*)d_in[2];
    float* out = (float*)d_out;

    dim3 grid(HH / TILE_H, BB, COUT / FG);   // (32, 4, 4) = 512 blocks
    dim3 block(BX, BY, 1);                   // 128 threads
    kaconv_kernel<<<grid, block>>>(x, A, Bc, out);
}

// round 3
// speedup vs baseline: 1.1704x; 1.1704x over previous
#include <cuda_runtime.h>

#define KK     3
#define CIN    16
#define COUT   16
#define HH     64
#define WW     64
#define BB     4

#define TILE_H 4          // output rows per block
#define BX     64
#define BY     2          // 128 threads; each thread does 2 rows, 2 channels
#define FG     2          // output channels per block (1 packed f32x2 pair)

typedef unsigned long long ull;

// ---------------- Blackwell packed f32x2 helpers ----------------
__device__ __forceinline__ ull pk2s(float v) {            // (v, v)
    ull r; asm("mov.b64 %0, {%1, %1};" : "=l"(r) : "f"(v)); return r;
}
__device__ __forceinline__ void upk2(ull v, float& lo, float& hi) {
    asm("mov.b64 {%0, %1}, %2;" : "=f"(lo), "=f"(hi) : "l"(v));
}
__device__ __forceinline__ ull pk2(float lo, float hi) {
    ull r; asm("mov.b64 %0, {%1, %2};" : "=l"(r) : "f"(lo), "f"(hi)); return r;
}
__device__ __forceinline__ ull ffma2(ull a, ull b, ull c) {
    ull d; asm("fma.rn.f32x2 %0, %1, %2, %3;" : "=l"(d) : "l"(a), "l"(b), "l"(c)); return d;
}
__device__ __forceinline__ ull fmul2(ull a, ull b) {
    ull d; asm("mul.rn.f32x2 %0, %1, %2;" : "=l"(d) : "l"(a), "l"(b)); return d;
}
__device__ __forceinline__ ull fadd2(ull a, ull b) {
    ull d; asm("add.rn.f32x2 %0, %1, %2;" : "=l"(d) : "l"(a), "l"(b)); return d;
}
__device__ __forceinline__ float frcp(float x) {
    float r; asm("rcp.approx.ftz.f32 %0, %1;" : "=f"(r) : "f"(x)); return r;
}

// SMEM:
//  sC: packed coefficients for this block's 2 output channels (f0, f0+1).
//      Per (c, p): 10 float2 entries:
//        k=0..5 : (A[f0][c][p][k],   A[f0+1][c][p][k])
//        k=6..9 : (Bc[f0][c][p][k-6], Bc[f0+1][c][p][k-6])
//      => 16*9*10 = 1440 float2 = 11520 B, 16B aligned for LDS.128
//  sX: all 16 input-channel tiles, (TILE_H+2)=6 rows x 66 cols
//      = 16*6*66 floats = 25344 B.  Total smem = 36.9 KB.
__global__ __launch_bounds__(BX * BY)
void kaconv_kernel(const float* __restrict__ x,
                   const float* __restrict__ A,
                   const float* __restrict__ Bc,
                   float* __restrict__ out) {
    __shared__ __align__(16) ull  sC[CIN * 9 * 10];      // 1440 ull = 11520 B
    __shared__ float              sX[CIN * (TILE_H + 2) * 66];

    const int tx  = threadIdx.x;
    const int ty  = threadIdx.y;
    const int tid = ty * BX + tx;
    const int h0  = blockIdx.x * TILE_H;
    const int b   = blockIdx.y;
    const int f0  = blockIdx.z * FG;

    // ---- stage packed coefficients ----
    float2* sCf = reinterpret_cast<float2*>(sC);
    for (int i = tid; i < CIN * 9 * 10; i += BX * BY) {
        int ii = i;
        const int k = ii % 10; ii /= 10;
        const int p = ii % 9;
        const int c = ii / 9;
        float lo, hi;
        if (k < 6) {
            lo = A[(( f0      * CIN + c) * 9 + p) * 6 + k];
            hi = A[(((f0 + 1) * CIN + c) * 9 + p) * 6 + k];
        } else {
            const int j = k - 6;
            lo = Bc[(( f0      * CIN + c) * 9 + p) * 4 + j];
            hi = Bc[(((f0 + 1) * CIN + c) * 9 + p) * 4 + j];
        }
        sCf[i] = make_float2(lo, hi);
    }

    // ---- stage all 16 input-channel tiles with zero-padded halo ----
    for (int i = tid; i < CIN * (TILE_H + 2) * 66; i += BX * BY) {
        const int col = i % 66;
        const int r   = (i / 66) % (TILE_H + 2);
        const int c   = i / (66 * (TILE_H + 2));
        const int gh  = h0 + r - 1;
        const int gw  = col - 1;
        float v = 0.0f;
        if (gh >= 0 && gh < HH && gw >= 0 && gw < WW)
            v = x[((b * CIN + c) * HH + gh) * WW + gw];
        sX[(c * (TILE_H + 2) + r) * 66 + col] = v;
    }
    __syncthreads();

    const ulonglong2* sC2 = reinterpret_cast<const ulonglong2*>(sC);
    const ull ABSM = 0x7FFFFFFF7FFFFFFFull;
    const ull ONE2 = 0x3F8000003F800000ull;   // (1.0f, 1.0f)

    // two pixels per thread: rows (h0 + 2*ty + 0/1), col tx; one f-pair
    ull acc0 = 0ull, acc1 = 0ull;

    #pragma unroll 1
    for (int c = 0; c < CIN; c++) {
        // 4 rows x 3 cols register window covers both pixels' 3x3 windows
        float xr[4][3];
        #pragma unroll
        for (int r = 0; r < 4; r++)
            #pragma unroll
            for (int j = 0; j < 3; j++)
                xr[r][j] = sX[(c * (TILE_H + 2) + 2 * ty + r) * 66 + (tx + j)];

        const ulonglong2* pc = sC2 + c * 45;   // (c*9 + p)*5 ulonglong2
        #pragma unroll
        for (int p = 0; p < 9; p++) {
            const int di = p / 3, dj = p % 3;
            const ulonglong2 u0 = pc[p * 5 + 0];  // {A0, A1}
            const ulonglong2 u1 = pc[p * 5 + 1];  // {A2, A3}
            const ulonglong2 u2 = pc[p * 5 + 2];  // {A4, A5}
            const ulonglong2 u3 = pc[p * 5 + 3];  // {B1, B2}
            const ulonglong2 u4 = pc[p * 5 + 4];  // {B3, B4}

            #pragma unroll
            for (int py = 0; py < 2; py++) {
                const ull X = pk2s(xr[py + di][dj]);

                // P = a0 + a1 x + ... + a5 x^5  (Horner, packed over f-pair)
                ull P = ffma2(u2.y, X, u2.x);
                P = ffma2(P, X, u1.y);
                P = ffma2(P, X, u1.x);
                P = ffma2(P, X, u0.y);
                P = ffma2(P, X, u0.x);

                // S = x*(b1 + x*(b2 + x*(b3 + x*b4)))
                ull T = ffma2(u4.y, X, u4.x);
                T = ffma2(T, X, u3.y);
                T = ffma2(T, X, u3.x);
                T = fmul2(T, X);

                // Q = 1 + |S|; R = 1/Q (per scalar via MUFU)
                const ull Qp = fadd2(ONE2, T & ABSM);
                float q0f, q1f; upk2(Qp, q0f, q1f);
                const ull R = pk2(frcp(q0f), frcp(q1f));

                if (py == 0) acc0 = ffma2(P, R, acc0);
                else         acc1 = ffma2(P, R, acc1);
            }
        }
    }

    // ---- write 2 pixels x 2 channels ----
    const int hA = h0 + 2 * ty;
    const int w  = tx;
    float a0, a1, b0, b1;
    upk2(acc0, a0, a1);   // pixel row hA,   channels f0 / f0+1
    upk2(acc1, b0, b1);   // pixel row hA+1, channels f0 / f0+1
    float* op = out + ((b * COUT + f0) * HH + hA) * WW + w;
    op[0]                = a0;
    op[WW]               = b0;
    op[HH * WW]          = a1;
    op[HH * WW + WW]     = b1;
}

extern "C" void kernel_launch(void* const* d_in, const int* in_sizes, int n_in,
                              void* d_out, int out_size) {
    const float* x  = (const float*)d_in[0];
    const float* A  = (const float*)d_in[1];
    const float* Bc = (const float*)d_in[2];
    float* out = (float*)d_out;

    dim3 grid(HH / TILE_H, BB, COUT / FG);   // (16, 4, 8) = 512 blocks
    dim3 block(BX, BY, 1);                   // 128 threads
    kaconv_kernel<<<grid, block>>>(x, A, Bc, out);
}